// round 6
// baseline (speedup 1.0000x reference)
#include <cuda_runtime.h>

#define BATCH   32
#define SEQ_LEN 4096
#define D_K     128
#define HALF    64                 // D_K / 2 rotation frequencies
#define ROW4    (D_K / 4)          // float4 per row = 32
#define ROW8    (D_K / 8)          // float8 chunks per row = 16
#define THREADS 256
#define POS_PER_BLOCK 2
#define BITERS  (BATCH / (THREADS / ROW8))   // 32 / 16 = 2 batch iters

// 256-bit global load with L2 evict-last (persisting) hint — sm_103 ptxas
// only accepts this modifier on .v8.b32/.v4.b64 loads.
__device__ __forceinline__ void ldg_evict_last_32B(const float4* p, float4& a, float4& b) {
    unsigned long long u0, u1, u2, u3;
    asm volatile("ld.global.L2::evict_last.v4.b64 {%0,%1,%2,%3}, [%4];"
                 : "=l"(u0), "=l"(u1), "=l"(u2), "=l"(u3) : "l"(p));
    a.x = __uint_as_float((unsigned)u0);  a.y = __uint_as_float((unsigned)(u0 >> 32));
    a.z = __uint_as_float((unsigned)u1);  a.w = __uint_as_float((unsigned)(u1 >> 32));
    b.x = __uint_as_float((unsigned)u2);  b.y = __uint_as_float((unsigned)(u2 >> 32));
    b.z = __uint_as_float((unsigned)u3);  b.w = __uint_as_float((unsigned)(u3 >> 32));
}

__global__ __launch_bounds__(THREADS) void rope_fused5_kernel(
    const float* __restrict__ x,
    const int*   __restrict__ token_positions,
    float*       __restrict__ out)
{
    // cs[0..63]  = {cos,sin} for position p0
    // cs[64..127]= {cos,sin} for position p1
    __shared__ float2 cs[POS_PER_BLOCK * HALF];

    const int t  = threadIdx.x;
    const int p0 = blockIdx.x * POS_PER_BLOCK;      // two adjacent positions

    const int u          = t & (ROW8 - 1);          // float8 chunk within row (0..15)
    const int b0         = t >> 4;                  // first batch slab (0..15)
    const int rowStride4 = SEQ_LEN * ROW4;          // float4 per batch slab
    const int baseA      = p0 * ROW4 + 2 * u;       // float4 index; p1 row = +ROW4

    const float4* __restrict__ x4 = (const float4*)x;
    float4*       __restrict__ o4 = (float4*)out;

    // ---- front-batch all 4 x 32B loads, L2 evict-last (pin x in L2) ----
    float4 v[2 * BITERS * 2];   // [iter][pos][half]
    #pragma unroll
    for (int i = 0; i < BITERS; i++) {
        const int idx = (b0 + 16 * i) * rowStride4 + baseA;
        ldg_evict_last_32B(&x4[idx],        v[4 * i + 0], v[4 * i + 1]); // pos p0
        ldg_evict_last_32B(&x4[idx + ROW4], v[4 * i + 2], v[4 * i + 3]); // pos p1
    }

    // ---- threads 0..127: one sincos each (64 freqs x 2 positions) ----
    if (t < POS_PER_BLOCK * HALF) {
        const int j = t & (HALF - 1);
        const int p = p0 + (t >> 6);

        // L = log2(10000)/64 split hi/lo; double-float exact j*L
        const double Ld   = 0.20762050593046014;
        const float  L_hi = (float)Ld;
        const float  L_lo = (float)(Ld - (double)L_hi);

        const float jf   = (float)j;
        const float ehi  = jf * L_hi;
        const float eerr = fmaf(jf, L_hi, -ehi);
        const float elo  = eerr + jf * L_lo;

        float inv = exp2f(-ehi);
        inv = inv - inv * (0.6931471805599453f * elo);

        const float ang = (float)token_positions[p] * inv;
        float s, c;
        sincosf(ang, &s, &c);
        cs[t] = make_float2(c, s);
    }
    __syncthreads();

    // Weights for chunk u (pairs 2u, 2u+1 in float4-of-cs units), per position.
    const float4* csp = (const float4*)cs;
    const float4 wA0 = csp[2 * u];
    const float4 wA1 = csp[2 * u + 1];
    const float4 wB0 = csp[32 + 2 * u];
    const float4 wB1 = csp[32 + 2 * u + 1];

    #pragma unroll
    for (int i = 0; i < BITERS; i++) {
        const int idx = (b0 + 16 * i) * rowStride4 + baseA;

        float4 a0 = v[4 * i + 0], a1 = v[4 * i + 1];
        float4 r0, r1;
        r0.x = a0.x * wA0.x - a0.y * wA0.y;  r0.y = a0.x * wA0.y + a0.y * wA0.x;
        r0.z = a0.z * wA0.z - a0.w * wA0.w;  r0.w = a0.z * wA0.w + a0.w * wA0.z;
        r1.x = a1.x * wA1.x - a1.y * wA1.y;  r1.y = a1.x * wA1.y + a1.y * wA1.x;
        r1.z = a1.z * wA1.z - a1.w * wA1.w;  r1.w = a1.z * wA1.w + a1.w * wA1.z;
        __stcs(&o4[idx],     r0);            // evict-first stores
        __stcs(&o4[idx + 1], r1);

        float4 b0v = v[4 * i + 2], b1v = v[4 * i + 3];
        float4 s0, s1;
        s0.x = b0v.x * wB0.x - b0v.y * wB0.y;  s0.y = b0v.x * wB0.y + b0v.y * wB0.x;
        s0.z = b0v.z * wB0.z - b0v.w * wB0.w;  s0.w = b0v.z * wB0.w + b0v.w * wB0.z;
        s1.x = b1v.x * wB1.x - b1v.y * wB1.y;  s1.y = b1v.x * wB1.y + b1v.y * wB1.x;
        s1.z = b1v.z * wB1.z - b1v.w * wB1.w;  s1.w = b1v.z * wB1.w + b1v.w * wB1.z;
        __stcs(&o4[idx + ROW4],     s0);
        __stcs(&o4[idx + ROW4 + 1], s1);
    }
}

extern "C" void kernel_launch(void* const* d_in, const int* in_sizes, int n_in,
                              void* d_out, int out_size) {
    const float* x   = (const float*)d_in[0];
    const int*   pos = (const int*)d_in[1];
    float*       out = (float*)d_out;

    rope_fused5_kernel<<<SEQ_LEN / POS_PER_BLOCK, THREADS>>>(x, pos, out);
}

// round 7
// speedup vs baseline: 1.2110x; 1.2110x over previous
#include <cuda_runtime.h>

#define SEQ_LEN 4096
#define D_K     128
#define HALF    64                  // rotation frequencies
#define ROW4    (D_K / 4)           // float4 per row = 32
#define THREADS 256
#define POSB    8                   // positions per block
#define HALFB   16                  // batches per block (32 / 2)
#define GRID    ((SEQ_LEN / POSB) * 2)   // 1024 = one full wave @ 7 blocks/SM

__global__ __launch_bounds__(THREADS, 7) void rope_wave_kernel(
    const float* __restrict__ x,
    const int*   __restrict__ token_positions,
    float*       __restrict__ out)
{
    __shared__ float2 cs[POSB * HALF];        // 512 {cos,sin}, 4 KB

    const int t  = threadIdx.x;
    const int pg = blockIdx.x >> 1;           // position group (0..511)
    const int bh = blockIdx.x & 1;            // batch half (0/1)
    const int p0 = pg * POSB;

    const int pp = t >> 5;                    // position offset within group (0..7)
    const int q  = t & 31;                    // float4 column (0..31)
    const int rowStride4 = SEQ_LEN * ROW4;    // 131072 float4 per batch slab
    const int base = bh * HALFB * rowStride4 + (p0 + pp) * ROW4 + q;

    const float4* __restrict__ x4 = (const float4*)x;
    float4*       __restrict__ o4 = (float4*)out;

    // Issue first two slab loads BEFORE the transcendental phase (overlap DRAM)
    float4 v0 = x4[base];
    float4 v1 = x4[base + rowStride4];

    // 2 sincos per thread: 8 positions x 64 freqs, double-float-exact angles
    #pragma unroll
    for (int e = t; e < POSB * HALF; e += THREADS) {
        const int j  = e & (HALF - 1);
        const int pe = e >> 6;

        const double Ld   = 0.20762050593046014;     // log2(1e4)/64
        const float  L_hi = (float)Ld;
        const float  L_lo = (float)(Ld - (double)L_hi);

        const float jf   = (float)j;
        const float ehi  = jf * L_hi;
        const float eerr = fmaf(jf, L_hi, -ehi);     // exact residual
        const float elo  = eerr + jf * L_lo;

        float inv = exp2f(-ehi);
        inv = inv - inv * (0.6931471805599453f * elo);

        const float ang = (float)token_positions[p0 + pe] * inv;
        float s, c;
        sincosf(ang, &s, &c);
        cs[e] = make_float2(c, s);
    }
    __syncthreads();

    // Loop-invariant weights: float4 #t = {cos2q, sin2q, cos2q+1, sin2q+1} of row pp
    const float4 cw = ((const float4*)cs)[t];

    // 16 batch slabs, contiguous 4KB chunk per block-iteration, depth-2 prefetch
    #pragma unroll
    for (int b = 0; b < HALFB; b++) {
        float4 vn;
        if (b + 2 < HALFB) vn = x4[base + (b + 2) * rowStride4];

        float4 r;
        r.x = v0.x * cw.x - v0.y * cw.y;
        r.y = v0.x * cw.y + v0.y * cw.x;
        r.z = v0.z * cw.z - v0.w * cw.w;
        r.w = v0.z * cw.w + v0.w * cw.z;
        __stcs(&o4[base + b * rowStride4], r);   // evict-first: protect x in L2

        v0 = v1;
        v1 = vn;
    }
}

extern "C" void kernel_launch(void* const* d_in, const int* in_sizes, int n_in,
                              void* d_out, int out_size) {
    const float* x   = (const float*)d_in[0];
    const int*   pos = (const int*)d_in[1];
    float*       out = (float*)d_out;

    rope_wave_kernel<<<GRID, THREADS>>>(x, pos, out);
}